// round 10
// baseline (speedup 1.0000x reference)
#include <cuda_runtime.h>
#include <cfloat>

typedef unsigned long long ull;

#define BB 4
#define NN 8192
#define KK 16
#define DD 64
#define NPTS (BB*NN)
#define GRID 48
#define CELLS (GRID*GRID*GRID)          // 110592
#define TOTCELLS (BB*CELLS)             // 442368 = 432*1024
#define NSCAN1 (TOTCELLS/1024)          // 432
#define ORG  (-6.144f)
#define HCEL (0.256f)
#define INVH (3.90625f)
#define NBLK2 256
#define BN_EPS 1e-5f

// ---------------- static scratch (no allocation) ----------------
__device__ int    g_cnt[TOTCELLS];      // histogram, then countdown cursor
__device__ int    g_start[TOTCELLS+1];  // global exclusive prefix
__device__ int    g_bsum[NSCAN1];
__device__ int    g_bsum2[NSCAN1];
__device__ int    g_pcell[NPTS];
__device__ float4 g_spos[NPTS];         // cell-sorted (x,y,z, bitcast local idx)
__device__ int    g_idx[NPTS*KK];       // knn neighbor lists (local idx)
__device__ float  g_a[NPTS*DD];         // u + max_k v
__device__ float  g_b2[NPTS*DD];        // u + min_k v
__device__ float  g_psum[NBLK2*DD];
__device__ float  g_psq[NBLK2*DD];
__device__ float  g_scale[DD];
__device__ float  g_shift[DD];

// ---------------- grid build ----------------
__global__ void zero_cnt_kernel() {
    g_cnt[blockIdx.x*1024 + threadIdx.x] = 0;
}

__global__ void hist_kernel(const float* __restrict__ x) {
    int p = blockIdx.x*256 + threadIdx.x;
    float px = x[p*3+0], py = x[p*3+1], pz = x[p*3+2];
    int cx = min(GRID-1, max(0, (int)floorf((px-ORG)*INVH)));
    int cy = min(GRID-1, max(0, (int)floorf((py-ORG)*INVH)));
    int cz = min(GRID-1, max(0, (int)floorf((pz-ORG)*INVH)));
    int cid = (cz*GRID + cy)*GRID + cx;
    g_pcell[p] = cid;
    atomicAdd(&g_cnt[(p>>13)*CELLS + cid], 1);
}

__global__ void scan1_kernel() {
    __shared__ int s[1024];
    int t = threadIdx.x;
    int g = blockIdx.x*1024 + t;
    int v = g_cnt[g];
    s[t] = v; __syncthreads();
    #pragma unroll
    for (int o = 1; o < 1024; o <<= 1) {
        int a = (t >= o) ? s[t-o] : 0;
        __syncthreads(); s[t] += a; __syncthreads();
    }
    g_start[g] = s[t] - v;
    if (t == 1023) g_bsum[blockIdx.x] = s[t];
}

__global__ void scan2_kernel() {
    __shared__ int s[512];
    int t = threadIdx.x;
    int v = (t < NSCAN1) ? g_bsum[t] : 0;
    s[t] = v; __syncthreads();
    #pragma unroll
    for (int o = 1; o < 512; o <<= 1) {
        int a = (t >= o) ? s[t-o] : 0;
        __syncthreads(); s[t] += a; __syncthreads();
    }
    if (t < NSCAN1) g_bsum2[t] = s[t] - v;
}

__global__ void scan3_kernel() {
    int g = blockIdx.x*1024 + threadIdx.x;
    g_start[g] += g_bsum2[blockIdx.x];
    if (g == 0) g_start[TOTCELLS] = NPTS;
}

__global__ void scatter_kernel(const float* __restrict__ x) {
    int p = blockIdx.x*256 + threadIdx.x;
    int gc = (p>>13)*CELLS + g_pcell[p];
    int pos = atomicAdd(&g_cnt[gc], -1) - 1;
    int slot = g_start[gc] + pos;
    g_spos[slot] = make_float4(x[p*3+0], x[p*3+1], x[p*3+2],
                               __int_as_float(p & (NN-1)));
}

// ---------------- grid KNN (exact, k=16, warp-cooperative) ----------------
__device__ __forceinline__ unsigned fkey(float d) {
    unsigned s = __float_as_uint(d);
    return s ^ (unsigned)(((int)s >> 31) | 0x80000000);
}
__device__ __forceinline__ float unfkey(unsigned u) {
    unsigned s = (u & 0x80000000u) ? (u ^ 0x80000000u) : ~u;
    return __uint_as_float(s);
}

// One warp = 32 consecutive cell-sorted queries. The warp scans a shared
// (warp-uniform) box of cells; candidates are loaded coalesced 32-at-a-time
// and broadcast via shfl; each lane maintains its own top-16 key list.
__global__ void __launch_bounds__(256) knn_grid_kernel() {
    int t = blockIdx.x*256 + threadIdx.x;     // global sorted slot (lane-owned query)
    int lane = threadIdx.x & 31;
    int b = t >> 13;                          // warp-uniform (8192 % 32 == 0)
    float4 q = g_spos[t];
    float qx = q.x, qy = q.y, qz = q.z;
    float qsq = fmaf(qz, qz, fmaf(qy, qy, qx*qx));
    int qi = __float_as_int(q.w);
    int cx = min(GRID-1, max(0, (int)floorf((qx-ORG)*INVH)));
    int cy = min(GRID-1, max(0, (int)floorf((qy-ORG)*INVH)));
    int cz = min(GRID-1, max(0, (int)floorf((qz-ORG)*INVH)));

    ull keys[KK];
    #pragma unroll
    for (int s = 0; s < KK; ++s) keys[s] = ~0ull;
    float d15 = FLT_MAX;
    const int cbase = b*CELLS;

    // process a contiguous slot range [s0,s1): coalesced loads + shfl broadcast
    auto scan_range = [&](int s0, int s1) {
        for (int base = s0; base < s1; base += 32) {
            int cnt = s1 - base; if (cnt > 32) cnt = 32;   // warp-uniform
            float4 p = make_float4(0.f, 0.f, 0.f, 0.f);
            if (base + lane < s1) p = g_spos[base + lane];
            float sqj_own = fmaf(p.z, p.z, fmaf(p.y, p.y, p.x*p.x)); // same fma chain as before
            #pragma unroll
            for (int j = 0; j < 32; ++j) {
                if (j >= cnt) break;                        // uniform break
                float px = __shfl_sync(0xffffffffu, p.x, j);
                float py = __shfl_sync(0xffffffffu, p.y, j);
                float pz = __shfl_sync(0xffffffffu, p.z, j);
                float sj = __shfl_sync(0xffffffffu, sqj_own, j);
                int   pi = __shfl_sync(0xffffffffu, __float_as_int(p.w), j);
                float dot = fmaf(pz, qz, fmaf(py, qy, px*qx));
                float dd  = fmaf(-2.f, dot, qsq + sj);      // reference formula
                ull key = ((ull)fkey(dd) << 32) | (unsigned)pi;
                if (key < keys[KK-1]) {
                    #pragma unroll
                    for (int i2 = 0; i2 < KK; ++i2) {
                        if (key < keys[i2]) { ull tmp = keys[i2]; keys[i2] = key; key = tmp; }
                    }
                    d15 = unfkey((unsigned)(keys[KK-1] >> 32));
                }
            }
        }
    };

    auto scan_row = [&](int z, int y, int xa, int xb) {
        xa = max(xa, 0); xb = min(xb, GRID-1);
        if (xa > xb) return;
        int rb = cbase + (z*GRID + y)*GRID;
        scan_range(g_start[rb + xa], g_start[rb + xb + 1]);
    };

    // warp-uniform initial box: union of all lanes' cells, +-1, clamped
    int x0 = max(__reduce_min_sync(0xffffffffu, cx) - 1, 0);
    int x1 = min(__reduce_max_sync(0xffffffffu, cx) + 1, GRID-1);
    int y0 = max(__reduce_min_sync(0xffffffffu, cy) - 1, 0);
    int y1 = min(__reduce_max_sync(0xffffffffu, cy) + 1, GRID-1);
    int z0 = max(__reduce_min_sync(0xffffffffu, cz) - 1, 0);
    int z1 = min(__reduce_max_sync(0xffffffffu, cz) + 1, GRID-1);

    for (int z = z0; z <= z1; ++z)
        for (int y = y0; y <= y1; ++y)
            scan_row(z, y, x0, x1);

    while (true) {
        // per-lane exact stop bound vs warp-uniform processed box
        float m = 1e30f;
        if (x0 > 0)      m = fminf(m, qx - (ORG + x0*HCEL));
        if (x1 < GRID-1) m = fminf(m, (ORG + (x1+1)*HCEL) - qx);
        if (y0 > 0)      m = fminf(m, qy - (ORG + y0*HCEL));
        if (y1 < GRID-1) m = fminf(m, (ORG + (y1+1)*HCEL) - qy);
        if (z0 > 0)      m = fminf(m, qz - (ORG + z0*HCEL));
        if (z1 < GRID-1) m = fminf(m, (ORG + (z1+1)*HCEL) - qz);
        bool done = (d15 <= m*m);            // NaN d15 (under-filled) -> false
        if (__all_sync(0xffffffffu, done)) break;

        int X0 = max(x0-1, 0), X1 = min(x1+1, GRID-1);
        int Y0 = max(y0-1, 0), Y1 = min(y1+1, GRID-1);
        int Z0 = max(z0-1, 0), Z1 = min(z1+1, GRID-1);
        for (int z = Z0; z <= Z1; ++z) {
            bool znew = (z < z0) || (z > z1);
            for (int y = Y0; y <= Y1; ++y) {
                if (znew || y < y0 || y > y1) {
                    scan_row(z, y, X0, X1);           // entirely new row
                } else {
                    if (X0 < x0) scan_row(z, y, X0, x0-1);
                    if (X1 > x1) scan_row(z, y, x1+1, X1);
                }
            }
        }
        x0 = X0; x1 = X1; y0 = Y0; y1 = Y1; z0 = Z0; z1 = Z1;
    }

    long long ob = ((long long)(b*NN + qi))*KK;
    #pragma unroll
    for (int s = 0; s < KK; ++s) g_idx[ob + s] = (int)(keys[s] & 0xFFFFFFFFull);
}

// ---------------- gather + BN partial stats (v computed on the fly) ----------------
__global__ void __launch_bounds__(256) gather_stats_kernel(
        const float* __restrict__ x, const float* __restrict__ W,
        const float* __restrict__ bias) {
    __shared__ float s_sum[8][DD];
    __shared__ float s_sq[8][DD];
    int lane = threadIdx.x & 31;
    int wrp  = threadIdx.x >> 5;
    int gw   = blockIdx.x*8 + wrp;
    int c0 = lane, c1 = lane + 32;

    float ws0[3], ws1[3], wd0[3], wd1[3];
    #pragma unroll
    for (int c = 0; c < 3; ++c) {
        ws0[c] = __ldg(&W[(3+c)*DD + c0]) + __ldg(&W[(6+c)*DD + c0]);
        ws1[c] = __ldg(&W[(3+c)*DD + c1]) + __ldg(&W[(6+c)*DD + c1]);
        wd0[c] = __ldg(&W[c*DD + c0]) - __ldg(&W[(3+c)*DD + c0]);
        wd1[c] = __ldg(&W[c*DD + c1]) - __ldg(&W[(3+c)*DD + c1]);
    }
    float b0 = __ldg(&bias[c0]), b1 = __ldg(&bias[c1]);

    float accs0 = 0.f, accs1 = 0.f, accq0 = 0.f, accq1 = 0.f;

    for (int i = gw; i < NPTS; i += NBLK2*8) {
        int b  = i >> 13;
        int qi = i & (NN-1);
        const float* xb = x + (size_t)b*NN*3;
        float qx2 = xb[qi*3+0], qy2 = xb[qi*3+1], qz2 = xb[qi*3+2];
        float u0 = fmaf(qz2, wd0[2], fmaf(qy2, wd0[1], fmaf(qx2, wd0[0], b0)));
        float u1 = fmaf(qz2, wd1[2], fmaf(qy2, wd1[1], fmaf(qx2, wd1[0], b1)));

        int nid = g_idx[(size_t)i*KK + (lane & 15)];
        float nx = xb[nid*3+0], ny = xb[nid*3+1], nz = xb[nid*3+2];

        float s10 = 0.f, s11 = 0.f, s20 = 0.f, s21 = 0.f;
        float mx0 = -FLT_MAX, mx1 = -FLT_MAX, mn0 = FLT_MAX, mn1 = FLT_MAX;
        #pragma unroll
        for (int n = 0; n < KK; ++n) {
            float xn = __shfl_sync(0xffffffffu, nx, n);
            float yn = __shfl_sync(0xffffffffu, ny, n);
            float zn = __shfl_sync(0xffffffffu, nz, n);
            float v0 = fmaf(zn, ws0[2], fmaf(yn, ws0[1], xn*ws0[0]));
            float v1 = fmaf(zn, ws1[2], fmaf(yn, ws1[1], xn*ws1[0]));
            s10 += v0; s20 = fmaf(v0, v0, s20);
            mx0 = fmaxf(mx0, v0); mn0 = fminf(mn0, v0);
            s11 += v1; s21 = fmaf(v1, v1, s21);
            mx1 = fmaxf(mx1, v1); mn1 = fminf(mn1, v1);
        }
        size_t o = (size_t)i*DD;
        g_a[o + c0]  = u0 + mx0;  g_a[o + c1]  = u1 + mx1;
        g_b2[o + c0] = u0 + mn0;  g_b2[o + c1] = u1 + mn1;

        accs0 += fmaf((float)KK, u0, s10);
        accs1 += fmaf((float)KK, u1, s11);
        accq0 += (float)KK*u0*u0 + 2.f*u0*s10 + s20;
        accq1 += (float)KK*u1*u1 + 2.f*u1*s11 + s21;
    }

    s_sum[wrp][c0] = accs0;  s_sum[wrp][c1] = accs1;
    s_sq[wrp][c0]  = accq0;  s_sq[wrp][c1]  = accq1;
    __syncthreads();

    if (threadIdx.x < DD) {
        float s = 0.f;
        #pragma unroll
        for (int k = 0; k < 8; ++k) s += s_sum[k][threadIdx.x];
        g_psum[blockIdx.x*DD + threadIdx.x] = s;
    } else if (threadIdx.x < 2*DD) {
        int d = threadIdx.x - DD;
        float s = 0.f;
        #pragma unroll
        for (int k = 0; k < 8; ++k) s += s_sq[k][d];
        g_psq[blockIdx.x*DD + d] = s;
    }
}

// ---------------- finalize BN stats (parallel) ----------------
__global__ void stats_kernel(const float* __restrict__ gamma,
                             const float* __restrict__ beta) {
    __shared__ float ss[4][DD];
    __shared__ float sq[4][DD];
    int t = threadIdx.x;          // 256
    int d = t & 63, ch = t >> 6;
    float s = 0.f, q = 0.f;
    for (int k = ch; k < NBLK2; k += 4) {
        s += g_psum[k*DD + d];
        q += g_psq[k*DD + d];
    }
    ss[ch][d] = s; sq[ch][d] = q;
    __syncthreads();
    if (t < DD) {
        float S = ss[0][t] + ss[1][t] + ss[2][t] + ss[3][t];
        float Q = sq[0][t] + sq[1][t] + sq[2][t] + sq[3][t];
        const float inv = 1.f / (float)((long long)NPTS * KK);
        float mean = S * inv;
        float var  = Q * inv - mean*mean;
        float sc   = __ldg(&gamma[t]) * rsqrtf(var + BN_EPS);
        g_scale[t] = sc;
        g_shift[t] = __ldg(&beta[t]) - mean * sc;
    }
}

// ---------------- output: BN affine + relu + folded max-pool ----------------
__global__ void out_kernel(float* __restrict__ out) {
    int gid = blockIdx.x*256 + threadIdx.x;
    int d = gid & 63;
    float sc = g_scale[d];
    float val = (sc >= 0.f) ? g_a[gid] : g_b2[gid];
    out[gid] = fmaxf(fmaf(sc, val, g_shift[d]), 0.f);
}

// ---------------- launch ----------------
extern "C" void kernel_launch(void* const* d_in, const int* in_sizes, int n_in,
                              void* d_out, int out_size) {
    const float* x     = (const float*)d_in[0];
    const float* W     = (const float*)d_in[1];
    const float* b     = (const float*)d_in[2];
    const float* gamma = (const float*)d_in[3];
    const float* beta  = (const float*)d_in[4];
    float* out = (float*)d_out;

    zero_cnt_kernel<<<NSCAN1, 1024>>>();
    hist_kernel<<<NPTS/256, 256>>>(x);
    scan1_kernel<<<NSCAN1, 1024>>>();
    scan2_kernel<<<1, 512>>>();
    scan3_kernel<<<NSCAN1, 1024>>>();
    scatter_kernel<<<NPTS/256, 256>>>(x);
    knn_grid_kernel<<<NPTS/256, 256>>>();
    gather_stats_kernel<<<NBLK2, 256>>>(x, W, b);
    stats_kernel<<<1, 256>>>(gamma, beta);
    out_kernel<<<(NPTS*DD)/256, 256>>>(out);
}